// round 5
// baseline (speedup 1.0000x reference)
#include <cuda_runtime.h>

// Dynamic filter layer: out[b,i,j,c] = sum_{di,dj} x[b,i+di,j+dj,c] * flow[b,i,j,di*K+dj]
// Shapes fixed by the dataset: B=8, H=W=256, C=64, K=5, Ho=Wo=252, fp32.

#define KS 5
#define NB 8
#define NH 256
#define NW 256
#define NC 64
#define HO 252
#define WO 252

#define ROWS_PB 28          // output rows per block (252 = 9*28)
#define NPAIR  (ROWS_PB/2)  // 14 row-pair iterations

// Duplicated-tap flow layout in smem (per pixel): dr-runs 16B-aligned.
#define PX_STRIDE 60        // floats per pixel (240 B)
#define DR_STRIDE 12        // floats per dr-run (48 B)

__device__ __forceinline__ void fma2(unsigned long long& d, unsigned long long a, unsigned long long b) {
    asm("fma.rn.f32x2 %0, %1, %2, %0;" : "+l"(d) : "l"(a), "l"(b));
}

// Stage one output-row-pair of flow into smem with tap duplication.
__device__ __forceinline__ void stage_flow(float* d0, float* d1,
                                           const float* f0, const float* f1,
                                           int nr, int tid) {
    for (int idx = tid; idx < nr; idx += 256) {
        const int px  = idx / 25;
        const int tap = idx - px * 25;
        const int dr  = tap / 5;
        const int dj  = tap - dr * 5;
        const int o   = px * PX_STRIDE + dr * DR_STRIDE + dj * 2;
        const float v0 = f0[idx], v1 = f1[idx];
        *(float2*)&d0[o] = make_float2(v0, v0);
        *(float2*)&d1[o] = make_float2(v1, v1);
    }
}

// Block: 256 threads = 16 channel-groups (float4) x 16 j-units (2 px each).
// Block tile: 28 output rows x 32 cols x 64 ch, computed as 14 row-pairs with a
// rolling 6-row x-window held in registers (2 new rows loaded per pair).
// Flow double-buffered in smem; one __syncthreads per pair.
// Grid: (8, 9, 8).
__global__ __launch_bounds__(256, 4)
void dfl_kernel(const float* __restrict__ x,
                const float* __restrict__ flow,
                float* __restrict__ out) {
    // [buffer][row-in-pair][pixel*PX_STRIDE] : 2*2*32*60 floats = 30 KB
    __shared__ __align__(16) float fsb[2][2][32 * PX_STRIDE];

    const int tid = threadIdx.x;
    const int b   = blockIdx.z;
    const int i0  = blockIdx.y * ROWS_PB;    // first output row of block
    const int jb  = blockIdx.x * 32;         // first output col of block
    const int njb = min(32, WO - jb);        // 32 or 28
    const int nr  = njb * 25;

    const int cg = tid & 15;                 // channel group (float4)
    const int jl = tid >> 4;                 // j-unit 0..15
    const bool jok = (jb + jl * 2) < WO;     // store guard (edge block)
    const int jlc = jok ? jl : (njb / 2 - 1);// clamped unit for loads/compute
    const int j0  = jb + jlc * 2;
    const int c0  = cg * 4;

    const long rowstride = (long)NW * NC;    // x row stride in floats
    const char* xbase =
        (const char*)(x + (((long)b * NH + i0) * NW + j0) * NC + c0);
    const float* fbase = flow + (((long)b * HO + i0) * WO + jb) * 25;
    const long frow = (long)WO * 25;

    // Prologue: stage flow pair 0, load x rows 0..5 into the window.
    stage_flow(fsb[0][0], fsb[0][1], fbase, fbase + frow, nr, tid);

    ulonglong2 xr[6];
#pragma unroll
    for (int cc = 0; cc < 6; ++cc) xr[cc].x = xr[cc].y = 0ull;  // placate compiler
#pragma unroll
    for (int rr = 0; rr < 6; ++rr)
#pragma unroll
        for (int cc = 0; cc < 6; ++cc)
            ((ulonglong2*)xr)[0] = xr[0];    // no-op; real loads below
#pragma unroll
    for (int rr = 0; rr < 6; ++rr)
#pragma unroll
        for (int cc = 0; cc < 6; ++cc)
            ;                                 // (kept simple below)
    // real prologue loads: rows 0..5 -- flatten to one array of 6 rows x 6 cols
    ulonglong2 w[6][6];
#pragma unroll
    for (int rr = 0; rr < 6; ++rr)
#pragma unroll
        for (int cc = 0; cc < 6; ++cc)
            w[rr][cc] = *(const ulonglong2*)(xbase + ((long)rr * rowstride + cc * NC) * 4);

    __syncthreads();

#pragma unroll 2
    for (int p = 0; p < NPAIR; ++p) {
        const int buf = p & 1;

        // Accumulators: 2 rows x 2 cols x (2 x f32x2)
        unsigned long long acc[2][2][2];
#pragma unroll
        for (int r = 0; r < 2; ++r)
#pragma unroll
            for (int q = 0; q < 2; ++q) { acc[r][q][0] = 0ull; acc[r][q][1] = 0ull; }

        const float* fpx[2] = { &fsb[buf][0][jlc * 2 * PX_STRIDE],
                                &fsb[buf][1][jlc * 2 * PX_STRIDE] };

#pragma unroll
        for (int di = 0; di < 6; ++di) {
#pragma unroll
            for (int r = 0; r < 2; ++r) {
                const int dr = di - r;
                if (dr < 0 || dr >= KS) continue;
                const float* frp = fpx[r] + dr * DR_STRIDE;
#pragma unroll
                for (int q = 0; q < 2; ++q) {
                    const float* fp = frp + q * PX_STRIDE;
                    const ulonglong2 t01 = *(const ulonglong2*)(fp);
                    const ulonglong2 t23 = *(const ulonglong2*)(fp + 4);
                    const unsigned long long t4 = *(const unsigned long long*)(fp + 8);
                    fma2(acc[r][q][0], w[di][q + 0].x, t01.x);
                    fma2(acc[r][q][1], w[di][q + 0].y, t01.x);
                    fma2(acc[r][q][0], w[di][q + 1].x, t01.y);
                    fma2(acc[r][q][1], w[di][q + 1].y, t01.y);
                    fma2(acc[r][q][0], w[di][q + 2].x, t23.x);
                    fma2(acc[r][q][1], w[di][q + 2].y, t23.x);
                    fma2(acc[r][q][0], w[di][q + 3].x, t23.y);
                    fma2(acc[r][q][1], w[di][q + 3].y, t23.y);
                    fma2(acc[r][q][0], w[di][q + 4].x, t4);
                    fma2(acc[r][q][1], w[di][q + 4].y, t4);
                }
            }
        }

        // Stores (guarded for the edge block)
        if (jok) {
#pragma unroll
            for (int r = 0; r < 2; ++r)
#pragma unroll
                for (int q = 0; q < 2; ++q) {
                    ulonglong2 v; v.x = acc[r][q][0]; v.y = acc[r][q][1];
                    *(ulonglong2*)(out + (((long)b * HO + (i0 + 2 * p + r)) * WO + (j0 + q)) * NC + c0) = v;
                }
        }

        if (p + 1 < NPAIR) {
            // Stage next flow pair into the other buffer (readers of that
            // buffer finished before the previous sync).
            const float* fnext = fbase + (long)(2 * (p + 1)) * frow;
            stage_flow(fsb[buf ^ 1][0], fsb[buf ^ 1][1], fnext, fnext + frow, nr, tid);

            // Slide x window down by 2 rows; load rows 2p+6, 2p+7.
#pragma unroll
            for (int rr = 0; rr < 4; ++rr)
#pragma unroll
                for (int cc = 0; cc < 6; ++cc)
                    w[rr][cc] = w[rr + 2][cc];
#pragma unroll
            for (int rr = 4; rr < 6; ++rr)
#pragma unroll
                for (int cc = 0; cc < 6; ++cc)
                    w[rr][cc] = *(const ulonglong2*)(xbase + ((long)(2 * p + 2 + rr) * rowstride + cc * NC) * 4);

            __syncthreads();
        }
    }
}

extern "C" void kernel_launch(void* const* d_in, const int* in_sizes, int n_in,
                              void* d_out, int out_size) {
    const float* x    = (const float*)d_in[0];
    const float* flow = (const float*)d_in[1];
    // d_in[2] = ksize (int32) — fixed at 5 for this dataset.
    float* out = (float*)d_out;

    dim3 grid((WO + 31) / 32, HO / ROWS_PB, NB);   // (8, 9, 8)
    dfl_kernel<<<grid, 256>>>(x, flow, out);
}

// round 6
// speedup vs baseline: 5.4382x; 5.4382x over previous
#include <cuda_runtime.h>

// Dynamic filter layer: out[b,i,j,c] = sum_{di,dj} x[b,i+di,j+dj,c] * flow[b,i,j,di*K+dj]
// Shapes fixed by the dataset: B=8, H=W=256, C=64, K=5, Ho=Wo=252, fp32.

#define KS 5
#define NB 8
#define NH 256
#define NW 256
#define NC 64
#define HO 252
#define WO 252

#define RPB 3               // output rows per block (252 = 3*84)

// Duplicated-tap flow layout in smem (per pixel): dr-runs 16B-aligned.
//   pixel stride 60 floats (240B), dr-run stride 12 floats (48B),
//   tap dj at +dj*2 (duplicated float2 pair).
#define PX_STRIDE 60
#define DR_STRIDE 12

__device__ __forceinline__ void fma2(unsigned long long& d, unsigned long long a, unsigned long long b) {
    asm("fma.rn.f32x2 %0, %1, %2, %0;" : "+l"(d) : "l"(a), "l"(b));
}

// Block: 256 threads = 16 channel-groups (float4) x 16 j-units (2 px each).
// Thread tile: 3(i) x 2(j) pixels x 4 channels. Block tile: 3 rows x 32 cols x 64 ch.
// Per-di row processing: only one 6-float4 x row live at a time (no R4-style
// persistent window -> no spills). Grid: (8, 84, 8).
__global__ __launch_bounds__(256, 3)
void dfl_kernel(const float* __restrict__ x,
                const float* __restrict__ flow,
                float* __restrict__ out) {
    // 3 output rows x 32 pixels of duplicated flow: 3*32*60*4B = 23 KB
    __shared__ __align__(16) float fs[RPB][32 * PX_STRIDE];

    const int tid = threadIdx.x;
    const int b   = blockIdx.z;
    const int i0  = blockIdx.y * RPB;        // first output row of block
    const int jb  = blockIdx.x * 32;         // first output col of block
    const int njb = min(32, WO - jb);        // 32 or 28
    const int nr  = njb * 25;

    // Cooperative flow staging with tap duplication (3 rows)
    {
        const float* f0 = flow + (((long)b * HO + i0) * WO + jb) * 25;
        const long frow = (long)WO * 25;
        for (int idx = tid; idx < nr; idx += 256) {
            const int px  = idx / 25;
            const int tap = idx - px * 25;
            const int dr  = tap / 5;
            const int dj  = tap - dr * 5;
            const int o   = px * PX_STRIDE + dr * DR_STRIDE + dj * 2;
            const float v0 = f0[idx];
            const float v1 = f0[idx + frow];
            const float v2 = f0[idx + 2 * frow];
            *(float2*)&fs[0][o] = make_float2(v0, v0);
            *(float2*)&fs[1][o] = make_float2(v1, v1);
            *(float2*)&fs[2][o] = make_float2(v2, v2);
        }
    }
    __syncthreads();

    const int cg  = tid & 15;                // channel group: 16 lanes broadcast LDS
    const int jl  = tid >> 4;                // j-unit 0..15
    const bool jok = (jb + jl * 2) < WO;     // store guard (edge block only)
    const int jlc = jok ? jl : (njb / 2 - 1);// clamped unit for loads/compute
    const int j0  = jb + jlc * 2;
    const int c0  = cg * 4;

    const long rowstride = (long)NW * NC;    // x row stride in floats
    const char* xbase =
        (const char*)(x + (((long)b * NH + i0) * NW + j0) * NC + c0);

    // Accumulators: 3 rows x 2 cols x (2 x f32x2) = 6 float4 outputs = 24 regs
    unsigned long long acc[RPB][2][2];
#pragma unroll
    for (int r = 0; r < RPB; ++r)
#pragma unroll
        for (int q = 0; q < 2; ++q) { acc[r][q][0] = 0ull; acc[r][q][1] = 0ull; }

#pragma unroll
    for (int di = 0; di < RPB + KS - 1; ++di) {   // 7 input rows feed 3 output rows
        // 6-wide float4 window of this input row (24 regs), reused across
        // the valid (r, dr) pairs and 2 output cols.
        ulonglong2 xr[6];
#pragma unroll
        for (int cc = 0; cc < 6; ++cc)
            xr[cc] = *(const ulonglong2*)(xbase + ((long)di * rowstride + cc * NC) * 4);

#pragma unroll
        for (int r = 0; r < RPB; ++r) {
            const int dr = di - r;           // tap row for output row r
            if (dr < 0 || dr >= KS) continue;
            const float* frp = &fs[r][jlc * 2 * PX_STRIDE + dr * DR_STRIDE];
#pragma unroll
            for (int q = 0; q < 2; ++q) {
                const float* fp = frp + q * PX_STRIDE;
                const ulonglong2 t01 = *(const ulonglong2*)(fp);      // dj=0,1
                const ulonglong2 t23 = *(const ulonglong2*)(fp + 4);  // dj=2,3
                const unsigned long long t4 = *(const unsigned long long*)(fp + 8);
                fma2(acc[r][q][0], xr[q + 0].x, t01.x);
                fma2(acc[r][q][1], xr[q + 0].y, t01.x);
                fma2(acc[r][q][0], xr[q + 1].x, t01.y);
                fma2(acc[r][q][1], xr[q + 1].y, t01.y);
                fma2(acc[r][q][0], xr[q + 2].x, t23.x);
                fma2(acc[r][q][1], xr[q + 2].y, t23.x);
                fma2(acc[r][q][0], xr[q + 3].x, t23.y);
                fma2(acc[r][q][1], xr[q + 3].y, t23.y);
                fma2(acc[r][q][0], xr[q + 4].x, t4);
                fma2(acc[r][q][1], xr[q + 4].y, t4);
            }
        }
    }

    // Store 6 float4 results (guarded for the edge block)
    if (jok) {
#pragma unroll
        for (int r = 0; r < RPB; ++r)
#pragma unroll
            for (int q = 0; q < 2; ++q) {
                ulonglong2 v; v.x = acc[r][q][0]; v.y = acc[r][q][1];
                *(ulonglong2*)(out + (((long)b * HO + (i0 + r)) * WO + (j0 + q)) * NC + c0) = v;
            }
    }
}

extern "C" void kernel_launch(void* const* d_in, const int* in_sizes, int n_in,
                              void* d_out, int out_size) {
    const float* x    = (const float*)d_in[0];
    const float* flow = (const float*)d_in[1];
    // d_in[2] = ksize (int32) — fixed at 5 for this dataset.
    float* out = (float*)d_out;

    dim3 grid((WO + 31) / 32, HO / RPB, NB);   // (8, 84, 8)
    dfl_kernel<<<grid, 256>>>(x, flow, out);
}

// round 7
// speedup vs baseline: 6.5249x; 1.1998x over previous
#include <cuda_runtime.h>

// Dynamic filter layer: out[b,i,j,c] = sum_{di,dj} x[b,i+di,j+dj,c] * flow[b,i,j,di*K+dj]
// Shapes fixed by the dataset: B=8, H=W=256, C=64, K=5, Ho=Wo=252, fp32.

#define KS 5
#define NB 8
#define NH 256
#define NW 256
#define NC 64
#define HO 252
#define WO 252

#define RPB 3               // output rows per block (252 = 3*84)

// Pair-packed flow smem layout: per pixel-PAIR pp (2 adjacent output cols),
// per tap (dr,dj): float4 { f(2pp,t), f(2pp,t), f(2pp+1,t), f(2pp+1,t) }.
// One LDS.128 -> duplicated f32x2 multipliers for BOTH pixels of the pair.
// Per pp: 25 taps * 16B = 400B (16B-aligned stride).
#define PP_STRIDE 100        // floats per pixel-pair (25 float4)

__device__ __forceinline__ void fma2(unsigned long long& d, unsigned long long a, unsigned long long b) {
    asm("fma.rn.f32x2 %0, %1, %2, %0;" : "+l"(d) : "l"(a), "l"(b));
}

// Block: 128 threads = 16 channel-groups (float4) x 8 j-units (4 px each).
// Thread tile: 3(i) x 4(j) pixels x 4 channels = 12 float4 outputs.
// Block tile: 3 rows x 32 cols x 64 ch. Grid: (8, 84, 8).
__global__ __launch_bounds__(128, 5)
void dfl_kernel(const float* __restrict__ x,
                const float* __restrict__ flow,
                float* __restrict__ out) {
    // 3 output rows x 16 pixel-pairs x 25 packed taps: 3*16*400B = 19.2 KB
    __shared__ __align__(16) float fs[RPB][16 * PP_STRIDE];

    const int tid = threadIdx.x;
    const int b   = blockIdx.z;
    const int i0  = blockIdx.y * RPB;        // first output row of block
    const int jb  = blockIdx.x * 32;         // first output col of block
    const int njb = min(32, WO - jb);        // 32 or 28
    const int nr  = njb * 25;

    // Cooperative flow staging: duplicate each tap into its pixel-pair slot.
    {
        const float* f0 = flow + (((long)b * HO + i0) * WO + jb) * 25;
        const long frow = (long)WO * 25;
        for (int idx = tid; idx < nr; idx += 128) {
            const int px  = idx / 25;
            const int tap = idx - px * 25;
            const int o   = (px >> 1) * PP_STRIDE + tap * 4 + (px & 1) * 2;
            const float v0 = f0[idx];
            const float v1 = f0[idx + frow];
            const float v2 = f0[idx + 2 * frow];
            *(float2*)&fs[0][o] = make_float2(v0, v0);
            *(float2*)&fs[1][o] = make_float2(v1, v1);
            *(float2*)&fs[2][o] = make_float2(v2, v2);
        }
    }
    __syncthreads();

    const int cg  = tid & 15;                // channel group: 16 lanes broadcast LDS
    const int jl  = tid >> 4;                // j-unit 0..7 (4 px each)
    const bool jok = (jb + jl * 4) < WO;     // store guard (edge block: jl==7)
    const int jlc = jok ? jl : 6;            // clamped unit for loads/compute
    const int j0  = jb + jlc * 4;
    const int c0  = cg * 4;

    const long rowstride = (long)NW * NC;    // x row stride in floats
    const char* xbase =
        (const char*)(x + (((long)b * NH + i0) * NW + j0) * NC + c0);

    // Accumulators: 3 rows x 4 cols x (2 x f32x2) = 12 float4 outputs (48 regs)
    unsigned long long acc[RPB][4][2];
#pragma unroll
    for (int r = 0; r < RPB; ++r)
#pragma unroll
        for (int q = 0; q < 4; ++q) { acc[r][q][0] = 0ull; acc[r][q][1] = 0ull; }

    // Base pointers for this thread's two pixel-pairs (pp = 2*jlc, 2*jlc+1)
    const float* fpp0[RPB] = { &fs[0][jlc * 2 * PP_STRIDE],
                               &fs[1][jlc * 2 * PP_STRIDE],
                               &fs[2][jlc * 2 * PP_STRIDE] };

#pragma unroll
    for (int di = 0; di < RPB + KS - 1; ++di) {   // 7 input rows feed 3 output rows
        // 8-wide float4 window of this input row (32 regs), reused across
        // 5 dj taps x 4 output cols.
        ulonglong2 xr[8];
#pragma unroll
        for (int cc = 0; cc < 8; ++cc)
            xr[cc] = *(const ulonglong2*)(xbase + ((long)di * rowstride + cc * NC) * 4);

#pragma unroll
        for (int r = 0; r < RPB; ++r) {
            const int dr = di - r;           // tap row for output row r
            if (dr < 0 || dr >= KS) continue;
#pragma unroll
            for (int pp = 0; pp < 2; ++pp) { // pixel pairs (q=2pp, 2pp+1)
                const float* fp = fpp0[r] + pp * PP_STRIDE + dr * 5 * 4;
#pragma unroll
                for (int dj = 0; dj < KS; ++dj) {
                    // One LDS.128: {f(q0),f(q0),f(q1),f(q1)} for tap (dr,dj)
                    const ulonglong2 fv = *(const ulonglong2*)(fp + dj * 4);
                    const int q0 = 2 * pp, q1 = 2 * pp + 1;
                    fma2(acc[r][q0][0], xr[q0 + dj].x, fv.x);
                    fma2(acc[r][q0][1], xr[q0 + dj].y, fv.x);
                    fma2(acc[r][q1][0], xr[q1 + dj].x, fv.y);
                    fma2(acc[r][q1][1], xr[q1 + dj].y, fv.y);
                }
            }
        }
    }

    // Store 12 float4 results (guarded for the edge block)
    if (jok) {
#pragma unroll
        for (int r = 0; r < RPB; ++r)
#pragma unroll
            for (int q = 0; q < 4; ++q) {
                ulonglong2 v; v.x = acc[r][q][0]; v.y = acc[r][q][1];
                *(ulonglong2*)(out + (((long)b * HO + (i0 + r)) * WO + (j0 + q)) * NC + c0) = v;
            }
    }
}

extern "C" void kernel_launch(void* const* d_in, const int* in_sizes, int n_in,
                              void* d_out, int out_size) {
    const float* x    = (const float*)d_in[0];
    const float* flow = (const float*)d_in[1];
    // d_in[2] = ksize (int32) — fixed at 5 for this dataset.
    float* out = (float*)d_out;

    dim3 grid((WO + 31) / 32, HO / RPB, NB);   // (8, 84, 8)
    dfl_kernel<<<grid, 128>>>(x, flow, out);
}

// round 8
// speedup vs baseline: 6.6107x; 1.0131x over previous
#include <cuda_runtime.h>

// Dynamic filter layer: out[b,i,j,c] = sum_{di,dj} x[b,i+di,j+dj,c] * flow[b,i,j,di*K+dj]
// Shapes fixed by the dataset: B=8, H=W=256, C=64, K=5, Ho=Wo=252, fp32.

#define KS 5
#define NB 8
#define NH 256
#define NW 256
#define NC 64
#define HO 252
#define WO 252

#define RPB 3               // output rows per block (252 = 3*84)

// Pair-packed flow smem layout: per pixel-PAIR pp (2 adjacent output cols),
// per tap (dr,dj): float4 { f(2pp,t), f(2pp,t), f(2pp+1,t), f(2pp+1,t) }.
// One LDS.128 -> duplicated f32x2 multipliers for BOTH pixels of the pair.
#define PP_STRIDE 100        // floats per pixel-pair (25 float4 = 400 B)

__device__ __forceinline__ void fma2(unsigned long long& d, unsigned long long a, unsigned long long b) {
    asm("fma.rn.f32x2 %0, %1, %2, %0;" : "+l"(d) : "l"(a), "l"(b));
}

// Block: 128 threads = 16 channel-groups (float4) x 8 j-units (4 px each).
// Thread tile: 3(i) x 4(j) x 4(c) = 12 float4 outputs.
// x row window DOUBLE-BUFFERED: prefetch row di+1 while consuming row di,
// hiding the ~234cyc L2 latency behind ~190cyc of FFMA2 work per row.
// Grid: (8, 84, 8).
__global__ __launch_bounds__(128, 4)
void dfl_kernel(const float* __restrict__ x,
                const float* __restrict__ flow,
                float* __restrict__ out) {
    // 3 output rows x 16 pixel-pairs x 25 packed taps: 19.2 KB
    __shared__ __align__(16) float fs[RPB][16 * PP_STRIDE];

    const int tid = threadIdx.x;
    const int b   = blockIdx.z;
    const int i0  = blockIdx.y * RPB;        // first output row of block
    const int jb  = blockIdx.x * 32;         // first output col of block
    const int njb = min(32, WO - jb);        // 32 or 28
    const int nr  = njb * 25;

    // Cooperative flow staging: duplicate each tap into its pixel-pair slot.
    {
        const float* f0 = flow + (((long)b * HO + i0) * WO + jb) * 25;
        const long frow = (long)WO * 25;
        for (int idx = tid; idx < nr; idx += 128) {
            const int px  = idx / 25;
            const int tap = idx - px * 25;
            const int o   = (px >> 1) * PP_STRIDE + tap * 4 + (px & 1) * 2;
            const float v0 = f0[idx];
            const float v1 = f0[idx + frow];
            const float v2 = f0[idx + 2 * frow];
            *(float2*)&fs[0][o] = make_float2(v0, v0);
            *(float2*)&fs[1][o] = make_float2(v1, v1);
            *(float2*)&fs[2][o] = make_float2(v2, v2);
        }
    }
    __syncthreads();

    const int cg  = tid & 15;                // channel group: 16 lanes broadcast LDS
    const int jl  = tid >> 4;                // j-unit 0..7 (4 px each)
    const bool jok = (jb + jl * 4) < WO;     // store guard (edge block: jl==7)
    const int jlc = jok ? jl : 6;            // clamped unit for loads/compute
    const int j0  = jb + jlc * 4;
    const int c0  = cg * 4;

    const long rowstride = (long)NW * NC;    // x row stride in floats
    const char* xbase =
        (const char*)(x + (((long)b * NH + i0) * NW + j0) * NC + c0);

    // Accumulators: 3 rows x 4 cols x (2 x f32x2) = 12 float4 outputs (48 regs)
    unsigned long long acc[RPB][4][2];
#pragma unroll
    for (int r = 0; r < RPB; ++r)
#pragma unroll
        for (int q = 0; q < 4; ++q) { acc[r][q][0] = 0ull; acc[r][q][1] = 0ull; }

    // Double-buffered 8-wide float4 row window (2 x 32 regs)
    ulonglong2 xr[2][8];
#pragma unroll
    for (int cc = 0; cc < 8; ++cc)
        xr[0][cc] = *(const ulonglong2*)(xbase + (cc * NC) * 4);

#pragma unroll
    for (int di = 0; di < RPB + KS - 1; ++di) {   // 7 input rows feed 3 output rows
        const int cur = di & 1;

        // Prefetch next row into the other buffer BEFORE consuming this one.
        if (di + 1 < RPB + KS - 1) {
#pragma unroll
            for (int cc = 0; cc < 8; ++cc)
                xr[cur ^ 1][cc] =
                    *(const ulonglong2*)(xbase + (((long)(di + 1)) * rowstride + cc * NC) * 4);
        }

#pragma unroll
        for (int r = 0; r < RPB; ++r) {
            const int dr = di - r;           // tap row for output row r
            if (dr < 0 || dr >= KS) continue;
            const float* frp = &fs[r][jlc * 2 * PP_STRIDE + dr * 5 * 4];
#pragma unroll
            for (int pp = 0; pp < 2; ++pp) { // pixel pairs (q = 2pp, 2pp+1)
                const float* fp = frp + pp * PP_STRIDE;
#pragma unroll
                for (int dj = 0; dj < KS; ++dj) {
                    // One LDS.128: {f(q0),f(q0),f(q1),f(q1)} for tap (dr,dj)
                    const ulonglong2 fv = *(const ulonglong2*)(fp + dj * 4);
                    const int q0 = 2 * pp, q1 = 2 * pp + 1;
                    fma2(acc[r][q0][0], xr[cur][q0 + dj].x, fv.x);
                    fma2(acc[r][q0][1], xr[cur][q0 + dj].y, fv.x);
                    fma2(acc[r][q1][0], xr[cur][q1 + dj].x, fv.y);
                    fma2(acc[r][q1][1], xr[cur][q1 + dj].y, fv.y);
                }
            }
        }
    }

    // Store 12 float4 results (guarded for the edge block)
    if (jok) {
#pragma unroll
        for (int r = 0; r < RPB; ++r)
#pragma unroll
            for (int q = 0; q < 4; ++q) {
                ulonglong2 v; v.x = acc[r][q][0]; v.y = acc[r][q][1];
                *(ulonglong2*)(out + (((long)b * HO + (i0 + r)) * WO + (j0 + q)) * NC + c0) = v;
            }
    }
}

extern "C" void kernel_launch(void* const* d_in, const int* in_sizes, int n_in,
                              void* d_out, int out_size) {
    const float* x    = (const float*)d_in[0];
    const float* flow = (const float*)d_in[1];
    // d_in[2] = ksize (int32) — fixed at 5 for this dataset.
    float* out = (float*)d_out;

    dim3 grid((WO + 31) / 32, HO / RPB, NB);   // (8, 84, 8)
    dfl_kernel<<<grid, 128>>>(x, flow, out);
}

// round 10
// speedup vs baseline: 6.7606x; 1.0227x over previous
#include <cuda_runtime.h>

// Dynamic filter layer: out[b,i,j,c] = sum_{di,dj} x[b,i+di,j+dj,c] * flow[b,i,j,di*K+dj]
// Shapes fixed by the dataset: B=8, H=W=256, C=64, K=5, Ho=Wo=252, fp32.

#define KS 5
#define NB 8
#define NH 256
#define NW 256
#define NC 64
#define HO 252
#define WO 252

#define RPB 4               // output rows per block (252 = 4*63)

// Pair-packed flow smem layout: per pixel-PAIR pp (2 adjacent output cols),
// per tap (dr,dj): float4 { f(2pp,t), f(2pp,t), f(2pp+1,t), f(2pp+1,t) }.
// One LDS.128 -> duplicated f32x2 multipliers for BOTH pixels of the pair.
#define PP_STRIDE 100        // floats per pixel-pair (25 float4 = 400 B)

__device__ __forceinline__ void fma2(unsigned long long& d, unsigned long long a, unsigned long long b) {
    asm("fma.rn.f32x2 %0, %1, %2, %0;" : "+l"(d) : "l"(a), "l"(b));
}

// Block: 128 threads = 16 channel-groups (float4) x 8 j-units (4 px each).
// Thread tile: 4(i) x 4(j) x 4(c) = 16 float4 outputs.
// Block tile: 4 rows x 32 cols x 64 ch. Single-buffered 8-float4 row window
// (only one row live at a time -> acc 64 + window 32 + temps fits 128 regs).
// Grid: (8, 63, 8).
__global__ __launch_bounds__(128, 4)
void dfl_kernel(const float* __restrict__ x,
                const float* __restrict__ flow,
                float* __restrict__ out) {
    // 4 output rows x 16 pixel-pairs x 25 packed taps: 4*16*400B = 25.6 KB
    __shared__ __align__(16) float fs[RPB][16 * PP_STRIDE];

    const int tid = threadIdx.x;
    const int b   = blockIdx.z;
    const int i0  = blockIdx.y * RPB;        // first output row of block
    const int jb  = blockIdx.x * 32;         // first output col of block
    const int njb = min(32, WO - jb);        // 32 or 28
    const int nr  = njb * 25;

    // Cooperative flow staging: duplicate each tap into its pixel-pair slot.
    {
        const float* f0 = flow + (((long)b * HO + i0) * WO + jb) * 25;
        const long frow = (long)WO * 25;
        for (int idx = tid; idx < nr; idx += 128) {
            const int px  = idx / 25;
            const int tap = idx - px * 25;
            const int o   = (px >> 1) * PP_STRIDE + tap * 4 + (px & 1) * 2;
#pragma unroll
            for (int r = 0; r < RPB; ++r) {
                const float v = f0[idx + r * frow];
                *(float2*)&fs[r][o] = make_float2(v, v);
            }
        }
    }
    __syncthreads();

    const int cg  = tid & 15;                // channel group: 16 lanes broadcast LDS
    const int jl  = tid >> 4;                // j-unit 0..7 (4 px each)
    const bool jok = (jb + jl * 4) < WO;     // store guard (edge block: jl==7)
    const int jlc = jok ? jl : 6;            // clamped unit for loads/compute
    const int j0  = jb + jlc * 4;
    const int c0  = cg * 4;

    const long rowstride = (long)NW * NC;    // x row stride in floats
    const char* xbase =
        (const char*)(x + (((long)b * NH + i0) * NW + j0) * NC + c0);

    // Accumulators: 4 rows x 4 cols x (2 x f32x2) = 16 float4 outputs (64 regs)
    unsigned long long acc[RPB][4][2];
#pragma unroll
    for (int r = 0; r < RPB; ++r)
#pragma unroll
        for (int q = 0; q < 4; ++q) { acc[r][q][0] = 0ull; acc[r][q][1] = 0ull; }

#pragma unroll
    for (int di = 0; di < RPB + KS - 1; ++di) {   // 8 input rows feed 4 output rows
        // 8-wide float4 window of this input row (32 regs), reused across
        // 5 dj taps x 4 output cols x up-to-4 output rows.
        ulonglong2 xr[8];
#pragma unroll
        for (int cc = 0; cc < 8; ++cc)
            xr[cc] = *(const ulonglong2*)(xbase + ((long)di * rowstride + cc * NC) * 4);

#pragma unroll
        for (int r = 0; r < RPB; ++r) {
            const int dr = di - r;           // tap row for output row r
            if (dr < 0 || dr >= KS) continue;
            const float* frp = &fs[r][jlc * 2 * PP_STRIDE + dr * 5 * 4];
#pragma unroll
            for (int pp = 0; pp < 2; ++pp) { // pixel pairs (q = 2pp, 2pp+1)
                const float* fp = frp + pp * PP_STRIDE;
#pragma unroll
                for (int dj = 0; dj < KS; ++dj) {
                    // One LDS.128: {f(q0),f(q0),f(q1),f(q1)} for tap (dr,dj)
                    const ulonglong2 fv = *(const ulonglong2*)(fp + dj * 4);
                    const int q0 = 2 * pp, q1 = 2 * pp + 1;
                    fma2(acc[r][q0][0], xr[q0 + dj].x, fv.x);
                    fma2(acc[r][q0][1], xr[q0 + dj].y, fv.x);
                    fma2(acc[r][q1][0], xr[q1 + dj].x, fv.y);
                    fma2(acc[r][q1][1], xr[q1 + dj].y, fv.y);
                }
            }
        }
    }

    // Store 16 float4 results (guarded for the edge block)
    if (jok) {
#pragma unroll
        for (int r = 0; r < RPB; ++r)
#pragma unroll
            for (int q = 0; q < 4; ++q) {
                ulonglong2 v; v.x = acc[r][q][0]; v.y = acc[r][q][1];
                *(ulonglong2*)(out + (((long)b * HO + (i0 + r)) * WO + (j0 + q)) * NC + c0) = v;
            }
    }
}

extern "C" void kernel_launch(void* const* d_in, const int* in_sizes, int n_in,
                              void* d_out, int out_size) {
    const float* x    = (const float*)d_in[0];
    const float* flow = (const float*)d_in[1];
    // d_in[2] = ksize (int32) — fixed at 5 for this dataset.
    float* out = (float*)d_out;

    dim3 grid((WO + 31) / 32, HO / RPB, NB);   // (8, 63, 8)
    dfl_kernel<<<grid, 128>>>(x, flow, out);
}

// round 11
// speedup vs baseline: 7.3435x; 1.0862x over previous
#include <cuda_runtime.h>
#include <cstdint>

// Dynamic filter layer: out[b,i,j,c] = sum_{di,dj} x[b,i+di,j+dj,c] * flow[b,i,j,di*K+dj]
// Shapes fixed by the dataset: B=8, H=W=256, C=64, K=5, Ho=Wo=252, fp32.

#define KS 5
#define NB 8
#define NH 256
#define NW 256
#define NC 64
#define HO 252
#define WO 252

#define RPB 4               // output rows per block (252 = 4*63)
#define NROWS (RPB + KS - 1)// 8 input rows per block
#define NSTAGE 3            // x slab ring depth

// Pair-packed flow smem layout (per pixel-pair, per tap): one LDS.128 yields
// duplicated f32x2 multipliers for two adjacent output pixels.
#define PP_STRIDE 100        // floats per pixel-pair (25 float4 = 400 B)

#define SLAB_BYTES 9216      // 36 cols x 64 ch x 4 B (full-width block)
#define SMEM_MBAR  0         // 3 mbarriers (8 B each), 64 B reserved
#define SMEM_SLAB  64
#define SMEM_FLOW  (SMEM_SLAB + NSTAGE * SLAB_BYTES)           // 27712
#define SMEM_TOTAL (SMEM_FLOW + RPB * 16 * PP_STRIDE * 4)      // + 25600 = 53312

__device__ __forceinline__ void fma2(unsigned long long& d, unsigned long long a, unsigned long long b) {
    asm("fma.rn.f32x2 %0, %1, %2, %0;" : "+l"(d) : "l"(a), "l"(b));
}
__device__ __forceinline__ uint32_t smem_u32(const void* p) {
    uint32_t a;
    asm("{ .reg .u64 t; cvta.to.shared.u64 t, %1; cvt.u32.u64 %0, t; }" : "=r"(a) : "l"(p));
    return a;
}
__device__ __forceinline__ void mbar_init(uint32_t mbar, uint32_t cnt) {
    asm volatile("mbarrier.init.shared.b64 [%0], %1;" :: "r"(mbar), "r"(cnt) : "memory");
}
__device__ __forceinline__ void mbar_expect_tx(uint32_t mbar, uint32_t bytes) {
    asm volatile("mbarrier.arrive.expect_tx.shared.b64 _, [%0], %1;" :: "r"(mbar), "r"(bytes) : "memory");
}
__device__ __forceinline__ void bulk_g2s(uint32_t dst, const void* src, uint32_t bytes, uint32_t mbar) {
    asm volatile("cp.async.bulk.shared::cta.global.mbarrier::complete_tx::bytes [%0], [%1], %2, [%3];"
                 :: "r"(dst), "l"(src), "r"(bytes), "r"(mbar) : "memory");
}
__device__ __forceinline__ void mbar_wait(uint32_t mbar, uint32_t parity) {
    uint32_t done;
    asm volatile("{\n\t.reg .pred p;\n\t"
                 "mbarrier.try_wait.parity.acquire.cta.shared::cta.b64 p, [%1], %2;\n\t"
                 "selp.b32 %0, 1, 0, p;\n\t}"
                 : "=r"(done) : "r"(mbar), "r"(parity) : "memory");
    if (!done) {
        asm volatile("{\n\t.reg .pred P1;\n\t"
                     "W_%=:\n\t"
                     "mbarrier.try_wait.parity.acquire.cta.shared::cta.b64 P1, [%0], %1, 0x989680;\n\t"
                     "@P1 bra.uni D_%=;\n\t"
                     "bra.uni W_%=;\n\t"
                     "D_%=:\n\t}"
                     :: "r"(mbar), "r"(parity) : "memory");
    }
}

// Block: 128 threads = 16 channel-groups (float4) x 8 j-units (4 px each).
// Thread tile: 4(i) x 4(j) x 4(c) = 16 float4 outputs. Grid: (8, 63, 8).
// x rows stream into a 3-slab smem ring via cp.async.bulk (one contiguous
// 9216B slab per input row); consumers read the 8-float4 window with LDS.
__global__ __launch_bounds__(128, 4)
void dfl_kernel(const float* __restrict__ x,
                const float* __restrict__ flow,
                float* __restrict__ out) {
    extern __shared__ __align__(16) char smem[];
    float* fs = (float*)(smem + SMEM_FLOW);            // [RPB][16*PP_STRIDE]
    const uint32_t smem_base = smem_u32(smem);
    const uint32_t mbar0 = smem_base + SMEM_MBAR;

    const int tid = threadIdx.x;
    const int b   = blockIdx.z;
    const int i0  = blockIdx.y * RPB;        // first output row of block
    const int jb  = blockIdx.x * 32;         // first output col of block
    const int njb = min(32, WO - jb);        // 32 or 28
    const int nr  = njb * 25;
    const int ncols = min(36, NW - jb);      // x cols staged (36 or 32)
    const uint32_t slab_bytes = ncols * NC * 4;

    // Init mbarriers, fence init->async proxy, then prefetch rows 0..2.
    if (tid == 0) {
        mbar_init(mbar0 + 0, 1);
        mbar_init(mbar0 + 8, 1);
        mbar_init(mbar0 + 16, 1);
        asm volatile("fence.proxy.async.shared::cta;" ::: "memory");
    }
    __syncthreads();
    const float* xrow0 = x + (((long)b * NH + i0) * NW + jb) * NC;
    if (tid == 0) {
#pragma unroll
        for (int s = 0; s < NSTAGE; ++s) {
            mbar_expect_tx(mbar0 + s * 8, slab_bytes);
            bulk_g2s(smem_base + SMEM_SLAB + s * SLAB_BYTES,
                     xrow0 + (long)s * NW * NC, slab_bytes, mbar0 + s * 8);
        }
    }

    // Stage flow (duplicated pair-packed) while the first slabs fly.
    {
        const float* f0 = flow + (((long)b * HO + i0) * WO + jb) * 25;
        const long frow = (long)WO * 25;
        for (int idx = tid; idx < nr; idx += 128) {
            const int px  = idx / 25;
            const int tap = idx - px * 25;
            const int o   = (px >> 1) * PP_STRIDE + tap * 4 + (px & 1) * 2;
#pragma unroll
            for (int r = 0; r < RPB; ++r) {
                const float v = f0[idx + r * frow];
                *(float2*)&fs[r * 16 * PP_STRIDE + o] = make_float2(v, v);
            }
        }
    }
    __syncthreads();

    const int cg  = tid & 15;                // channel group: 16 lanes broadcast LDS
    const int jl  = tid >> 4;                // j-unit 0..7 (4 px each)
    const bool jok = (jb + jl * 4) < WO;     // store guard (edge block: jl==7)
    const int jlc = jok ? jl : 6;            // clamped unit for loads/compute
    const int j0  = jb + jlc * 4;
    const int c0  = cg * 4;

    // Accumulators: 4 rows x 4 cols x (2 x f32x2) = 16 float4 outputs (64 regs)
    unsigned long long acc[RPB][4][2];
#pragma unroll
    for (int r = 0; r < RPB; ++r)
#pragma unroll
        for (int q = 0; q < 4; ++q) { acc[r][q][0] = 0ull; acc[r][q][1] = 0ull; }

    // Per-thread byte offset inside a slab for window col cc: (4*jlc+cc)*256 + cg*16
    const int thr_off = jlc * 4 * (NC * 4) + cg * 16;

#pragma unroll
    for (int di = 0; di < NROWS; ++di) {     // 8 input rows feed 4 output rows
        const int s  = di % NSTAGE;          // compile-time (full unroll)
        const int ph = (di / NSTAGE) & 1;
        mbar_wait(mbar0 + s * 8, ph);

        const char* slab = smem + SMEM_SLAB + s * SLAB_BYTES + thr_off;
        // 8-wide float4 window of this input row from smem (32 regs)
        ulonglong2 xr[8];
#pragma unroll
        for (int cc = 0; cc < 8; ++cc)
            xr[cc] = *(const ulonglong2*)(slab + cc * (NC * 4));

#pragma unroll
        for (int r = 0; r < RPB; ++r) {
            const int dr = di - r;           // tap row for output row r
            if (dr < 0 || dr >= KS) continue;
            const float* frp = &fs[r * 16 * PP_STRIDE + jlc * 2 * PP_STRIDE + dr * 5 * 4];
#pragma unroll
            for (int pp = 0; pp < 2; ++pp) { // pixel pairs (q = 2pp, 2pp+1)
                const float* fp = frp + pp * PP_STRIDE;
#pragma unroll
                for (int dj = 0; dj < KS; ++dj) {
                    const ulonglong2 fv = *(const ulonglong2*)(fp + dj * 4);
                    const int q0 = 2 * pp, q1 = 2 * pp + 1;
                    fma2(acc[r][q0][0], xr[q0 + dj].x, fv.x);
                    fma2(acc[r][q0][1], xr[q0 + dj].y, fv.x);
                    fma2(acc[r][q1][0], xr[q1 + dj].x, fv.y);
                    fma2(acc[r][q1][1], xr[q1 + dj].y, fv.y);
                }
            }
        }

        // Recycle slab s for row di+NSTAGE once everyone is done reading it.
        if (di + NSTAGE < NROWS) {
            __syncthreads();
            if (tid == 0) {
                mbar_expect_tx(mbar0 + s * 8, slab_bytes);
                bulk_g2s(smem_base + SMEM_SLAB + s * SLAB_BYTES,
                         xrow0 + (long)(di + NSTAGE) * NW * NC, slab_bytes, mbar0 + s * 8);
            }
        }
    }

    // Store 16 float4 results (guarded for the edge block)
    if (jok) {
#pragma unroll
        for (int r = 0; r < RPB; ++r)
#pragma unroll
            for (int q = 0; q < 4; ++q) {
                ulonglong2 v; v.x = acc[r][q][0]; v.y = acc[r][q][1];
                *(ulonglong2*)(out + (((long)b * HO + (i0 + r)) * WO + (j0 + q)) * NC + c0) = v;
            }
    }
}

extern "C" void kernel_launch(void* const* d_in, const int* in_sizes, int n_in,
                              void* d_out, int out_size) {
    const float* x    = (const float*)d_in[0];
    const float* flow = (const float*)d_in[1];
    // d_in[2] = ksize (int32) — fixed at 5 for this dataset.
    float* out = (float*)d_out;

    cudaFuncSetAttribute(dfl_kernel, cudaFuncAttributeMaxDynamicSharedMemorySize, SMEM_TOTAL);

    dim3 grid((WO + 31) / 32, HO / RPB, NB);   // (8, 63, 8)
    dfl_kernel<<<grid, 128, SMEM_TOTAL>>>(x, flow, out);
}